// round 16
// baseline (speedup 1.0000x reference)
#include <cuda_runtime.h>
#include <cuda_bf16.h>
#include <cstdint>

#define D 128
#define MAXN 50176
#define MAXE 1048576
#define LN_EPS 1e-5f

// ---------------------------------------------------------------------------
// Device scratch (allocation forbidden -> __device__ globals)
// ---------------------------------------------------------------------------
__device__ float4 g_agg4[(size_t)MAXN * (D / 4)];      // fp32 aggregation
__device__ int    g_cnt[MAXN + 1];
__device__ int    g_ptr[MAXN + 1];
__device__ int    g_fill[MAXN + 1];
__device__ int    g_src[MAXE];
__device__ int    g_bsum[64];
__device__ uint4  g_w1h[4096], g_w1l[4096];            // W1^T [128][256] bf16 planes
__device__ uint4  g_w2h[2048], g_w2l[2048];            // W^T  [128][128]
__device__ uint4  g_w3h[2048], g_w3l[2048];
__device__ uint4  g_w4h[2048], g_w4l[2048];

// ---------------------------------------------------------------------------
// PTX helpers (base ISA only: cp.async, ldmatrix, mma.sync — NO tcgen05)
// ---------------------------------------------------------------------------
__device__ __forceinline__ uint32_t smem_u32(const void* p) {
    uint32_t a;
    asm("{ .reg .u64 t; cvta.to.shared.u64 t, %1; cvt.u32.u64 %0, t; }"
        : "=r"(a) : "l"(p));
    return a;
}
#define CP_ASYNC16(s, g) \
    asm volatile("cp.async.cg.shared.global [%0], [%1], 16;" :: "r"(s), "l"(g))
#define CP_COMMIT() asm volatile("cp.async.commit_group;")
#define CP_WAIT0()  asm volatile("cp.async.wait_group 0;" ::: "memory")
#define CP_WAIT1()  asm volatile("cp.async.wait_group 1;" ::: "memory")
#define LDSM4(r, a) \
    asm volatile("ldmatrix.sync.aligned.m8n8.x4.shared.b16 {%0,%1,%2,%3}, [%4];" \
                 : "=r"((r)[0]), "=r"((r)[1]), "=r"((r)[2]), "=r"((r)[3]) : "r"(a))
// NOT volatile: pure register math. "+f" constraints carry true deps; ptxas
// is free to interleave independent accumulator chains for ILP.
#define MMA16816(c, a, b0, b1) \
    asm("mma.sync.aligned.m16n8k16.row.col.f32.bf16.bf16.f32 " \
        "{%0,%1,%2,%3},{%4,%5,%6,%7},{%8,%9},{%0,%1,%2,%3};" \
        : "+f"((c)[0]), "+f"((c)[1]), "+f"((c)[2]), "+f"((c)[3]) \
        : "r"((a)[0]), "r"((a)[1]), "r"((a)[2]), "r"((a)[3]), \
          "r"(b0), "r"(b1))

__device__ __forceinline__ void bsplit(float v, __nv_bfloat16& h, __nv_bfloat16& l) {
    h = __float2bfloat16(v);
    l = __float2bfloat16(v - __bfloat162float(h));
}
__device__ __forceinline__ uint32_t pack2(__nv_bfloat16 a, __nv_bfloat16 b) {
    return (uint32_t)__bfloat16_as_ushort(a) |
           ((uint32_t)__bfloat16_as_ushort(b) << 16);
}

// ---------------------------------------------------------------------------
// CSR build: zero -> hist -> block scan -> combine(+local bsum scan) -> fill
// ---------------------------------------------------------------------------
__global__ void zero_cnt_kernel(int n) {
    int i = blockIdx.x * blockDim.x + threadIdx.x;
    if (i <= n) g_cnt[i] = 0;
}

__global__ void hist_kernel(const int* __restrict__ ei, int E) {
    int e = blockIdx.x * blockDim.x + threadIdx.x;
    if (e < E) atomicAdd(&g_cnt[__ldg(ei + E + e)], 1);
}

// Per-block exclusive scan of g_cnt (1024/block); block totals -> g_bsum.
__global__ void scanA_kernel(int n) {
    __shared__ int s[1024];
    int t = threadIdx.x;
    int i = blockIdx.x * 1024 + t;
    int v = (i < n) ? g_cnt[i] : 0;
    s[t] = v;
    __syncthreads();
#pragma unroll
    for (int off = 1; off < 1024; off <<= 1) {
        int tv = (t >= off) ? s[t - off] : 0;
        __syncthreads();
        s[t] += tv;
        __syncthreads();
    }
    if (i < n) g_ptr[i] = s[t] - v;          // exclusive within block
    if (t == 1023) g_bsum[blockIdx.x] = s[t];
}

// Combine: each block locally prefixes the tiny g_bsum array (<=64 entries).
__global__ void scanC_kernel(int n, int nb) {
    __shared__ int pre;
    if (threadIdx.x == 0) {
        int a = 0;
        for (int b = 0; b < (int)blockIdx.x && b < nb; ++b) a += g_bsum[b];
        pre = a;
    }
    __syncthreads();
    int i = blockIdx.x * 1024 + threadIdx.x;
    if (i < n) {
        int v = g_ptr[i] + pre;
        g_ptr[i] = v;
        g_fill[i] = v;
    }
}

__global__ void fill_kernel(const int* __restrict__ ei, int E) {
    int e = blockIdx.x * blockDim.x + threadIdx.x;
    if (e < E) {
        int r = __ldg(ei + E + e);
        int pos = atomicAdd(&g_fill[r], 1);
        g_src[pos] = __ldg(ei + e);
    }
}

// One warp per receiver node: gather sender rows, sum in registers, store once.
__global__ void agg_kernel(const float* __restrict__ x, int N, int E) {
    int w = blockIdx.x * (blockDim.x >> 5) + (threadIdx.x >> 5);
    int lane = threadIdx.x & 31;
    if (w >= N) return;
    int start = g_ptr[w];
    int end = (w == N - 1) ? E : g_ptr[w + 1];
    float4 acc = make_float4(0.f, 0.f, 0.f, 0.f);
    for (int j = start; j < end; ++j) {
        int s = __ldg(g_src + j);            // warp-uniform broadcast
        float4 v = __ldg(((const float4*)(x + (size_t)s * D)) + lane);
        acc.x += v.x; acc.y += v.y; acc.z += v.z; acc.w += v.w;
    }
    g_agg4[(size_t)w * (D / 4) + lane] = acc;
}

// ---------------------------------------------------------------------------
// Fused W prep: all four W^T hi/lo planes in one launch.
// ---------------------------------------------------------------------------
__global__ void wprep_all(const float* __restrict__ W1, const float* __restrict__ W2,
                          const float* __restrict__ W3, const float* __restrict__ W4) {
    int i = blockIdx.x * blockDim.x + threadIdx.x;
    const float* W;
    __nv_bfloat16 *oh, *ol;
    int n, k, K, j;
    if (i < 32768) {                   // W1: n*256 + k
        W = W1; K = 256; j = i;
        oh = (__nv_bfloat16*)g_w1h; ol = (__nv_bfloat16*)g_w1l;
    } else {
        int r = i - 32768;
        int wsel = r >> 14;            // 0..2
        if (wsel > 2) return;
        j = r & 16383; K = 128;
        switch (wsel) {
            case 0: W = W2; oh = (__nv_bfloat16*)g_w2h; ol = (__nv_bfloat16*)g_w2l; break;
            case 1: W = W3; oh = (__nv_bfloat16*)g_w3h; ol = (__nv_bfloat16*)g_w3l; break;
            default: W = W4; oh = (__nv_bfloat16*)g_w4h; ol = (__nv_bfloat16*)g_w4l; break;
        }
    }
    n = j / K; k = j - n * K;
    __nv_bfloat16 h, l;
    bsplit(__ldg(W + k * 128 + n), h, l);
    oh[j] = h; ol[j] = l;
}

// ---------------------------------------------------------------------------
// Stage a 128x64 bf16 tile (row-major, strideElems) into swizzled smem.
// ---------------------------------------------------------------------------
__device__ __forceinline__ void load_tile(uint32_t sdst,
                                          const __nv_bfloat16* __restrict__ g,
                                          int strideElems, int tid) {
#pragma unroll
    for (int i = 0; i < 4; ++i) {
        int c = tid + i * 256;
        int row = c >> 3;
        int col8 = c & 7;
        uint32_t off = row * 128 + col8 * 16;
        uint32_t sw = off ^ ((off >> 3) & 0x70);
        CP_ASYNC16(sdst + sw, g + (size_t)row * strideElems + col8 * 8);
    }
}

// ---------------------------------------------------------------------------
// Fused 4-layer MLP (R13 config + non-volatile MMA): 128-row tile/CTA,
// 256 thr, 8 warps 4x2.
// smem: A chunks 0..3 (hi+lo 16KB each = 32KB/chunk) @ 0..128KB
//       W ping-pong bufs (32KB each)                 @ 128KB..192KB
// ---------------------------------------------------------------------------
#define SM_W  131072
#define SMEM_BYTES 196608

__global__ void __launch_bounds__(256, 1)
mlp_fused(const float* __restrict__ x,
          const float* __restrict__ b1, const float* __restrict__ b2,
          const float* __restrict__ b3, const float* __restrict__ b4,
          const float* __restrict__ gamma, const float* __restrict__ beta,
          float* __restrict__ outf, int N) {
    extern __shared__ char smem[];
    uint32_t sbase = smem_u32(smem);
    const int tid = threadIdx.x;
    const int lane = tid & 31, wid = tid >> 5;
    const int wm = wid >> 1, wn = wid & 1;
    const int warpRow = wm * 32;
    const int g = lane >> 2, t = lane & 3;
    const int row0 = blockIdx.x * 128;

    const __nv_bfloat16* WH[4] = {(const __nv_bfloat16*)g_w1h, (const __nv_bfloat16*)g_w2h,
                                  (const __nv_bfloat16*)g_w3h, (const __nv_bfloat16*)g_w4h};
    const __nv_bfloat16* WL[4] = {(const __nv_bfloat16*)g_w1l, (const __nv_bfloat16*)g_w2l,
                                  (const __nv_bfloat16*)g_w3l, (const __nv_bfloat16*)g_w4l};
    const float* BS[4] = {b1, b2, b3, b4};
    const int KK[4]  = {256, 128, 128, 128};
    const int KCH[4] = {4, 2, 2, 2};

    int aOff[2], aMask[2];
#pragma unroll
    for (int mt = 0; mt < 2; ++mt) {
        int r = warpRow + mt * 16 + (lane & 15);
        aOff[mt] = r * 128;
        aMask[mt] = (r & 7) << 4;
    }
    int wOff[4], wMask[4];
#pragma unroll
    for (int j = 0; j < 4; ++j) {
        int r = wn * 64 + j * 16 + ((lane >> 4) & 1) * 8 + (lane & 7);
        wOff[j] = r * 128;
        wMask[j] = (r & 7) << 4;
    }

    // Issue first W chunk (layer 0, chunk 0) -> buf 0, overlaps prologue.
    load_tile(sbase + SM_W,         WH[0], 256, tid);
    load_tile(sbase + SM_W + 16384, WL[0], 256, tid);
    CP_COMMIT();

    // Prologue: [x | agg] fp32 -> bf16 hi/lo planes, A chunks 0..3 (swizzled).
#pragma unroll
    for (int ch = 0; ch < 4; ++ch) {
        const float* src = (ch < 2) ? x : (const float*)g_agg4;
        int colBase = (ch & 1) * 64;
#pragma unroll
        for (int j = 0; j < 8; ++j) {
            int pos = tid + j * 256;             // 0..2047
            int row = pos >> 4;
            int c4 = (pos & 15) * 4;
            int gr = row0 + row;
            float4 v = make_float4(0.f, 0.f, 0.f, 0.f);
            if (gr < N) v = *(const float4*)(src + (size_t)gr * 128 + colBase + c4);
            __nv_bfloat16 h0, l0, h1, l1, h2, l2, h3, l3;
            bsplit(v.x, h0, l0); bsplit(v.y, h1, l1);
            bsplit(v.z, h2, l2); bsplit(v.w, h3, l3);
            uint32_t off = row * 128 + c4 * 2;
            uint32_t sw = off ^ ((off >> 3) & 0x70);
            *(uint2*)(smem + ch * 32768 + sw) = make_uint2(pack2(h0, h1), pack2(h2, h3));
            *(uint2*)(smem + ch * 32768 + 16384 + sw) = make_uint2(pack2(l0, l1), pack2(l2, l3));
        }
    }

    float acc[2][8][4];
#pragma unroll
    for (int mt = 0; mt < 2; ++mt)
#pragma unroll
        for (int nt = 0; nt < 8; ++nt)
#pragma unroll
            for (int k = 0; k < 4; ++k) acc[mt][nt][k] = 0.f;

    for (int L = 0; L < 4; ++L) {
        const int kch = KCH[L];
        for (int ch = 0; ch < kch; ++ch) {
            int nL = L, nch = ch + 1;
            if (nch == kch) { nL = L + 1; nch = 0; }
            if (nL < 4) {
                uint32_t wb = sbase + SM_W + ((ch + 1) & 1) * 32768;
                load_tile(wb,         WH[nL] + nch * 64, KK[nL], tid);
                load_tile(wb + 16384, WL[nL] + nch * 64, KK[nL], tid);
                CP_COMMIT();
                CP_WAIT1();
            } else {
                CP_WAIT0();
            }
            __syncthreads();

            uint32_t offA = sbase + ch * 32768;
            uint32_t offW = sbase + SM_W + (ch & 1) * 32768;
#pragma unroll
            for (int ks = 0; ks < 4; ++ks) {
                int kbA = ks * 32 + (lane & 16);
                int kbB = ks * 32 + ((lane & 8) << 1);
                uint32_t ah[2][4], al[2][4];
#pragma unroll
                for (int mt = 0; mt < 2; ++mt) {
                    LDSM4(ah[mt], offA + aOff[mt] + (kbA ^ aMask[mt]));
                    LDSM4(al[mt], offA + 16384 + aOff[mt] + (kbA ^ aMask[mt]));
                }
#pragma unroll
                for (int j = 0; j < 4; ++j) {
                    uint32_t wh[4], wl[4];
                    uint32_t aw = wOff[j] + (kbB ^ wMask[j]);
                    LDSM4(wh, offW + aw);
                    LDSM4(wl, offW + 16384 + aw);
#pragma unroll
                    for (int mt = 0; mt < 2; ++mt) {
                        MMA16816(acc[mt][j * 2 + 0], ah[mt], wh[0], wh[1]);
                        MMA16816(acc[mt][j * 2 + 1], ah[mt], wh[2], wh[3]);
                        MMA16816(acc[mt][j * 2 + 0], ah[mt], wl[0], wl[1]);
                        MMA16816(acc[mt][j * 2 + 1], ah[mt], wl[2], wl[3]);
                        MMA16816(acc[mt][j * 2 + 0], al[mt], wh[0], wh[1]);
                        MMA16816(acc[mt][j * 2 + 1], al[mt], wh[2], wh[3]);
                    }
                }
            }
            __syncthreads();
        }

        float bv[8][2];
#pragma unroll
        for (int nt = 0; nt < 8; ++nt) {
            int c = wn * 64 + nt * 8 + 2 * t;
            bv[nt][0] = BS[L][c];
            bv[nt][1] = BS[L][c + 1];
        }

        if (L < 3) {
#pragma unroll
            for (int mt = 0; mt < 2; ++mt)
#pragma unroll
                for (int h = 0; h < 2; ++h) {
                    int r = warpRow + mt * 16 + g + h * 8;
#pragma unroll
                    for (int nt = 0; nt < 8; ++nt) {
                        int cc = nt * 8 + 2 * t;
                        float v0 = fmaxf(acc[mt][nt][h * 2 + 0] + bv[nt][0], 0.f);
                        float v1 = fmaxf(acc[mt][nt][h * 2 + 1] + bv[nt][1], 0.f);
                        __nv_bfloat16 h0, l0, h1, l1;
                        bsplit(v0, h0, l0);
                        bsplit(v1, h1, l1);
                        uint32_t off = r * 128 + cc * 2;
                        uint32_t sw = off ^ ((off >> 3) & 0x70);
                        *(uint32_t*)(smem + wn * 32768 + sw) = pack2(h0, h1);
                        *(uint32_t*)(smem + wn * 32768 + 16384 + sw) = pack2(l0, l1);
                    }
                }
#pragma unroll
            for (int mt = 0; mt < 2; ++mt)
#pragma unroll
                for (int nt = 0; nt < 8; ++nt)
#pragma unroll
                    for (int k = 0; k < 4; ++k) acc[mt][nt][k] = 0.f;
        } else {
            float* ps = (float*)(smem + SM_W);
#pragma unroll
            for (int mt = 0; mt < 2; ++mt)
#pragma unroll
                for (int h = 0; h < 2; ++h) {
                    float s1 = 0.f, s2 = 0.f;
#pragma unroll
                    for (int nt = 0; nt < 8; ++nt) {
                        float v0 = acc[mt][nt][h * 2 + 0] + bv[nt][0];
                        float v1 = acc[mt][nt][h * 2 + 1] + bv[nt][1];
                        s1 += v0 + v1;
                        s2 += v0 * v0 + v1 * v1;
                    }
                    s1 += __shfl_xor_sync(0xffffffffu, s1, 1);
                    s2 += __shfl_xor_sync(0xffffffffu, s2, 1);
                    s1 += __shfl_xor_sync(0xffffffffu, s1, 2);
                    s2 += __shfl_xor_sync(0xffffffffu, s2, 2);
                    if (t == 0) {
                        int r = warpRow + mt * 16 + g + h * 8;
                        ps[r * 4 + wn * 2 + 0] = s1;
                        ps[r * 4 + wn * 2 + 1] = s2;
                    }
                }
            __syncthreads();

            float gv[8][2], betv[8][2];
#pragma unroll
            for (int nt = 0; nt < 8; ++nt) {
                int c = wn * 64 + nt * 8 + 2 * t;
                gv[nt][0] = gamma[c];   gv[nt][1] = gamma[c + 1];
                betv[nt][0] = beta[c];  betv[nt][1] = beta[c + 1];
            }
#pragma unroll
            for (int mt = 0; mt < 2; ++mt)
#pragma unroll
                for (int h = 0; h < 2; ++h) {
                    int r = warpRow + mt * 16 + g + h * 8;
                    int gr = row0 + r;
                    float S1 = ps[r * 4 + 0] + ps[r * 4 + 2];
                    float S2 = ps[r * 4 + 1] + ps[r * 4 + 3];
                    float mu = S1 * (1.0f / 128.0f);
                    float var = S2 * (1.0f / 128.0f) - mu * mu;
                    float inv = rsqrtf(var + LN_EPS);
                    if (gr < N) {
#pragma unroll
                        for (int nt = 0; nt < 8; ++nt) {
                            int c = wn * 64 + nt * 8 + 2 * t;
                            float v0 = acc[mt][nt][h * 2 + 0] + bv[nt][0];
                            float v1 = acc[mt][nt][h * 2 + 1] + bv[nt][1];
                            float2 o;
                            o.x = (v0 - mu) * inv * gv[nt][0] + betv[nt][0];
                            o.y = (v1 - mu) * inv * gv[nt][1] + betv[nt][1];
                            *(float2*)(outf + (size_t)gr * 128 + c) = o;
                        }
                    }
                }
        }
    }
}

// ---------------------------------------------------------------------------
// kernel_launch: CSR build -> gather-agg -> wprep -> fused MLP
// ---------------------------------------------------------------------------
extern "C" void kernel_launch(void* const* d_in, const int* in_sizes, int n_in,
                              void* d_out, int out_size) {
    const float* x     = (const float*)d_in[0];
    const int*   ei    = (const int*)d_in[1];
    const float* W1    = (const float*)d_in[2];
    const float* b1    = (const float*)d_in[3];
    const float* W2    = (const float*)d_in[4];
    const float* b2    = (const float*)d_in[5];
    const float* W3    = (const float*)d_in[6];
    const float* b3    = (const float*)d_in[7];
    const float* W4    = (const float*)d_in[8];
    const float* b4    = (const float*)d_in[9];
    const float* gamma = (const float*)d_in[10];
    const float* beta  = (const float*)d_in[11];
    float* out = (float*)d_out;

    int N = in_sizes[0] / D;
    int E = in_sizes[1] / 2;
    int GB = (N + 127) / 128;
    int NB = (N + 1023) / 1024;

    cudaFuncSetAttribute(mlp_fused, cudaFuncAttributeMaxDynamicSharedMemorySize, SMEM_BYTES);

    // CSR aggregation (replaces zero+atomic scatter)
    zero_cnt_kernel<<<(N + 1024) / 1024, 1024>>>(N);
    hist_kernel<<<(E + 255) / 256, 256>>>(ei, E);
    scanA_kernel<<<NB, 1024>>>(N);
    scanC_kernel<<<NB, 1024>>>(N, NB);
    fill_kernel<<<(E + 255) / 256, 256>>>(ei, E);
    agg_kernel<<<(N + 15) / 16, 512>>>(x, N, E);

    // W planes + fused MLP
    wprep_all<<<(32768 + 3 * 16384 + 255) / 256, 256>>>(W1, W2, W3, W4);
    mlp_fused<<<GB, 256, SMEM_BYTES>>>(x, b1, b2, b3, b4, gamma, beta, out, N);
}